// round 3
// baseline (speedup 1.0000x reference)
#include <cuda_runtime.h>

#define DINLINE __device__ __forceinline__

constexpr int N   = 50000;
constexpr int E   = 800000;
constexpr int F   = 128;
constexpr int DIM = 128;
constexpr int NF  = 4;
constexpr int ND  = 32;
constexpr int NL  = 3;
constexpr int NC  = 10;
constexpr int G   = 256;

constexpr int OFF_PRED = 0;
constexpr int OFF_ATT  = G * NC;            // 2560
constexpr int OFF_OUTS = OFF_ATT + NF * E;  // 3202560

// ------------------------- scratch (device globals, no cudaMalloc) ---------
__device__ float  g_state[N * DIM];
__device__ float  g_agg[N * DIM];
__device__ float  g_el[N * NF];
__device__ float  g_er[N * NF];
__device__ float  g_vl[NF * F];
__device__ float  g_vr[NF * F];
__device__ float  g_elb[NF];
__device__ float  g_erb[NF];
__device__ int    g_cnt[N];
__device__ int    g_rowptr[N + 1];
__device__ int    g_fill[N];
__device__ int    g_csr_src[E];
__device__ int    g_csr_eid[E];
__device__ float4 g_att_t[E];
__device__ float4 g_csr_att[E];
__device__ float  g_pooled[G * DIM];

DINLINE float sigm(float x)   { return __fdividef(1.f, 1.f + __expf(-x)); }
DINLINE float tanh_f(float x) { return 1.f - __fdividef(2.f, __expf(2.f * x) + 1.f); }

DINLINE float gru_out(float ir, float hr, float iz, float hz,
                      float inn, float hn, float h) {
    float r  = sigm(ir + hr);
    float z  = sigm(iz + hz);
    float nn = tanh_f(fmaf(r, hn, inn));
    return fmaf(z, h - nn, nn);   // (1-z)*nn + z*h
}

// ------------------------- K1: fold lin0/att into per-node vectors ---------
__global__ void k_pre(const float* __restrict__ lin0_W, const float* __restrict__ lin0_b,
                      const float* __restrict__ att_W,  const float* __restrict__ att_b) {
    int f = blockIdx.x;
    int k = threadIdx.x;
    const float* W  = lin0_W + (f * F + k) * DIM;
    const float* wl = att_W + f * 2 * DIM;
    const float* wr = wl + DIM;
    float sl = 0.f, sr = 0.f;
    for (int d = 0; d < DIM; d++) { float w = W[d]; sl = fmaf(w, wl[d], sl); sr = fmaf(w, wr[d], sr); }
    g_vl[f * F + k] = sl;
    g_vr[f * F + k] = sr;
    if (k == 0) {
        float bl = att_b[f], br = 0.f;
        const float* b0 = lin0_b + f * DIM;
        for (int d = 0; d < DIM; d++) { bl = fmaf(b0[d], wl[d], bl); br = fmaf(b0[d], wr[d], br); }
        g_elb[f] = bl;
        g_erb[f] = br;
    }
}

// ------------------------- K2: node init (enc GEMM + el/er GEMVs) ----------
constexpr int NPB = 16;  // nodes per block
__global__ __launch_bounds__(128) void k_init(const float* __restrict__ x,
                                              const float* __restrict__ enc_W,
                                              const float* __restrict__ enc_b) {
    extern __shared__ float sm[];
    float* ws = sm;                   // [k][c] : 128*128
    float* wv = ws + NF * F * ND;     // vl(512) then vr(512)
    float* xs = wv + 2 * NF * F;      // [k][NPB] : 128*16 (16B aligned offset)

    int tid = threadIdx.x;
    for (int i = tid; i < NF * F * ND; i += 128) {
        int c = i & 127, k = i >> 7;
        int f = c >> 5, d = c & 31;
        ws[i] = enc_W[(f * F + k) * ND + d];
    }
    for (int i = tid; i < 2 * NF * F; i += 128)
        wv[i] = (i < NF * F) ? g_vl[i] : g_vr[i - NF * F];

    int n0 = blockIdx.x * NPB;
    for (int n = 0; n < NPB; n++) {
        int node = n0 + n;
        xs[tid * NPB + n] = (node < N) ? x[node * F + tid] : 0.f;
    }
    __syncthreads();

    // each thread owns output column c for all NPB nodes
    int c = tid;
    float acc[NPB];
#pragma unroll
    for (int n = 0; n < NPB; n++) acc[n] = 0.f;
    for (int k = 0; k < F; k++) {
        float w = ws[k * 128 + c];
        const float4* xv = (const float4*)&xs[k * NPB];
#pragma unroll
        for (int q = 0; q < NPB / 4; q++) {
            float4 v = xv[q];
            acc[q * 4 + 0] = fmaf(w, v.x, acc[q * 4 + 0]);
            acc[q * 4 + 1] = fmaf(w, v.y, acc[q * 4 + 1]);
            acc[q * 4 + 2] = fmaf(w, v.z, acc[q * 4 + 2]);
            acc[q * 4 + 3] = fmaf(w, v.w, acc[q * 4 + 3]);
        }
    }
    int f = c >> 5, d = c & 31;
    float b = enc_b[f * ND + d];
#pragma unroll
    for (int n = 0; n < NPB; n++) {
        int node = n0 + n;
        if (node < N) g_state[node * DIM + c] = acc[n] + b;
    }

    // el/er: 128 threads = 16 nodes x 8 (4 factors x {l,r})
    int nn  = tid >> 3;
    int idx = tid & 7;
    int ff  = idx & 3;
    int isR = idx >> 2;
    const float* vec = &wv[isR * NF * F + ff * F];
    float a = 0.f;
    for (int k = 0; k < F; k++) a = fmaf(xs[k * NPB + nn], vec[k], a);
    int node = n0 + nn;
    if (node < N) {
        if (isR) g_er[node * NF + ff] = a + g_erb[ff];
        else     g_el[node * NF + ff] = a + g_elb[ff];
    }
}

// ------------------------- K3: per-edge attention --------------------------
__global__ void k_att(const int* __restrict__ ei, float* __restrict__ out_att) {
    int e = blockIdx.x * blockDim.x + threadIdx.x;
    if (e >= E) return;
    int s = ei[e], d = ei[E + e];
    float4 el = *(const float4*)&g_el[s * 4];
    float4 er = *(const float4*)&g_er[d * 4];
    float4 a;
    a.x = sigm(6.f * (el.x + er.x));
    a.y = sigm(6.f * (el.y + er.y));
    a.z = sigm(6.f * (el.z + er.z));
    a.w = sigm(6.f * (el.w + er.w));
    out_att[0 * E + e] = a.x;
    out_att[1 * E + e] = a.y;
    out_att[2 * E + e] = a.z;
    out_att[3 * E + e] = a.w;
    g_att_t[e] = a;
}

// ------------------------- K4: CSR build -----------------------------------
__global__ void k_zero_cnt() {
    int i = blockIdx.x * blockDim.x + threadIdx.x;
    if (i < N) g_cnt[i] = 0;
}
__global__ void k_hist(const int* __restrict__ ei) {
    int e = blockIdx.x * blockDim.x + threadIdx.x;
    if (e < E) atomicAdd(&g_cnt[ei[E + e]], 1);
}
__global__ __launch_bounds__(1024) void k_scan() {
    __shared__ int ssum[1024];
    int t = threadIdx.x;
    const int CH = (N + 1023) / 1024;  // 49
    int base = t * CH;
    int s = 0;
    for (int i = 0; i < CH; i++) { int idx = base + i; if (idx < N) s += g_cnt[idx]; }
    ssum[t] = s;
    __syncthreads();
    for (int off = 1; off < 1024; off <<= 1) {
        int v = (t >= off) ? ssum[t - off] : 0;
        __syncthreads();
        ssum[t] += v;
        __syncthreads();
    }
    int run = ssum[t] - s;  // exclusive
    for (int i = 0; i < CH; i++) {
        int idx = base + i;
        if (idx < N) {
            g_rowptr[idx] = run;
            g_fill[idx]   = run;
            run += g_cnt[idx];
        }
    }
    if (t == 1023) g_rowptr[N] = ssum[1023];
}
__global__ void k_scatter(const int* __restrict__ ei) {
    int e = blockIdx.x * blockDim.x + threadIdx.x;
    if (e >= E) return;
    int s = ei[e], d = ei[E + e];
    int pos = atomicAdd(&g_fill[d], 1);
    g_csr_src[pos] = s;
    g_csr_eid[pos] = e;
}
__global__ void k_csratt() {
    int p = blockIdx.x * blockDim.x + threadIdx.x;
    if (p < E) g_csr_att[p] = g_att_t[g_csr_eid[p]];
}

// ------------------------- K5: per-layer aggregation (warp per node) -------
__global__ __launch_bounds__(256) void k_agg() {
    int warp = (blockIdx.x * blockDim.x + threadIdx.x) >> 5;
    int lane = threadIdx.x & 31;
    if (warp >= N) return;
    int beg = g_rowptr[warp], end = g_rowptr[warp + 1];
    const float4* sp = (const float4*)g_state;
    int f = lane >> 3;
    float ax = 0.f, ay = 0.f, az = 0.f, aw = 0.f;
    for (int p = beg; p < end; p++) {
        int src  = __ldg(&g_csr_src[p]);
        float4 at = g_csr_att[p];
        float av = (f == 0) ? at.x : (f == 1) ? at.y : (f == 2) ? at.z : at.w;
        float4 v = sp[src * 32 + lane];
        ax = fmaf(av, v.x, ax);
        ay = fmaf(av, v.y, ay);
        az = fmaf(av, v.z, az);
        aw = fmaf(av, v.w, aw);
    }
    ((float4*)g_agg)[warp * 32 + lane] = make_float4(ax, ay, az, aw);
}

// ------------------------- K6: fused conv + GRU update ---------------------
__global__ __launch_bounds__(256) void k_update(
    const float* __restrict__ Wrel, const float* __restrict__ brel,
    const float* __restrict__ Wroot,
    const float* __restrict__ Wih, const float* __restrict__ Whh,
    const float* __restrict__ bih, const float* __restrict__ bhh, int l) {
    __shared__ __align__(16) float sWrel[32 * 32];
    __shared__ __align__(16) float sWroot[32 * 32];
    __shared__ __align__(16) float sWih[32 * 96];   // [j][i]
    __shared__ __align__(16) float sWhh[32 * 96];   // [j][i]
    __shared__ float sbrel[32], sbih[96], sbhh[96];
    __shared__ __align__(16) float as_[32 * 36];    // [j][node], pad 36
    __shared__ __align__(16) float os_[32 * 36];
    __shared__ __align__(16) float ms_[8 * 128];    // per-warp m staging

    int f   = blockIdx.y;
    int tid = threadIdx.x;

    const float* Wrel_g  = Wrel + (f * NL + l) * ND * ND;
    const float* Wroot_g = Wroot + (f * NL + l) * ND * ND;
    for (int i = tid; i < ND * ND; i += 256) { sWrel[i] = Wrel_g[i]; sWroot[i] = Wroot_g[i]; }
    const float* Wih_g = Wih + f * 3 * ND * ND;
    const float* Whh_g = Whh + f * 3 * ND * ND;
    for (int i = tid; i < 3 * ND * ND; i += 256) {
        int r = i >> 5, j = i & 31;
        sWih[j * 96 + r] = Wih_g[i];
        sWhh[j * 96 + r] = Whh_g[i];
    }
    if (tid < 32) sbrel[tid] = brel[(f * NL + l) * ND + tid];
    if (tid < 96) { sbih[tid] = bih[f * 96 + tid]; sbhh[tid] = bhh[f * 96 + tid]; }

    int n0 = blockIdx.x * 32;
    for (int u = tid; u < 1024; u += 256) {
        int j = u & 31, n = u >> 5, node = n0 + n;
        float a = 0.f, o = 0.f;
        if (node < N) {
            a = g_agg[node * DIM + f * ND + j];
            o = g_state[node * DIM + f * ND + j];
        }
        as_[j * 36 + n] = a;
        os_[j * 36 + n] = o;
    }
    __syncthreads();

    int w = tid >> 5, d = tid & 31, nl = w * 4;

    // m = relu(agg @ Wrel + brel + out @ Wroot), 4 nodes per lane
    float bm = sbrel[d];
    float m0 = bm, m1 = bm, m2 = bm, m3 = bm;
#pragma unroll 8
    for (int j = 0; j < 32; j++) {
        float4 a4 = *(const float4*)&as_[j * 36 + nl];
        float4 o4 = *(const float4*)&os_[j * 36 + nl];
        float wr = sWrel[j * 32 + d], wo = sWroot[j * 32 + d];
        m0 = fmaf(a4.x, wr, m0); m1 = fmaf(a4.y, wr, m1); m2 = fmaf(a4.z, wr, m2); m3 = fmaf(a4.w, wr, m3);
        m0 = fmaf(o4.x, wo, m0); m1 = fmaf(o4.y, wo, m1); m2 = fmaf(o4.z, wo, m2); m3 = fmaf(o4.w, wo, m3);
    }
    m0 = fmaxf(m0, 0.f); m1 = fmaxf(m1, 0.f); m2 = fmaxf(m2, 0.f); m3 = fmaxf(m3, 0.f);
    float* msw = &ms_[w * 128];
    *(float4*)&msw[d * 4] = make_float4(m0, m1, m2, m3);
    __syncwarp();

    // gi = m @ Wih.T + bih
    float b0 = sbih[d], b1 = sbih[32 + d], b2 = sbih[64 + d];
    float4 gi0 = make_float4(b0, b0, b0, b0);
    float4 gi1 = make_float4(b1, b1, b1, b1);
    float4 gi2 = make_float4(b2, b2, b2, b2);
#pragma unroll 8
    for (int j = 0; j < 32; j++) {
        float4 mj = *(const float4*)&msw[j * 4];
        float w0 = sWih[j * 96 + d], w1 = sWih[j * 96 + 32 + d], w2 = sWih[j * 96 + 64 + d];
        gi0.x = fmaf(mj.x, w0, gi0.x); gi0.y = fmaf(mj.y, w0, gi0.y); gi0.z = fmaf(mj.z, w0, gi0.z); gi0.w = fmaf(mj.w, w0, gi0.w);
        gi1.x = fmaf(mj.x, w1, gi1.x); gi1.y = fmaf(mj.y, w1, gi1.y); gi1.z = fmaf(mj.z, w1, gi1.z); gi1.w = fmaf(mj.w, w1, gi1.w);
        gi2.x = fmaf(mj.x, w2, gi2.x); gi2.y = fmaf(mj.y, w2, gi2.y); gi2.z = fmaf(mj.z, w2, gi2.z); gi2.w = fmaf(mj.w, w2, gi2.w);
    }

    // gh = h @ Whh.T + bhh  (h == current state)
    b0 = sbhh[d]; b1 = sbhh[32 + d]; b2 = sbhh[64 + d];
    float4 gh0 = make_float4(b0, b0, b0, b0);
    float4 gh1 = make_float4(b1, b1, b1, b1);
    float4 gh2 = make_float4(b2, b2, b2, b2);
#pragma unroll 8
    for (int j = 0; j < 32; j++) {
        float4 oj = *(const float4*)&os_[j * 36 + nl];
        float w0 = sWhh[j * 96 + d], w1 = sWhh[j * 96 + 32 + d], w2 = sWhh[j * 96 + 64 + d];
        gh0.x = fmaf(oj.x, w0, gh0.x); gh0.y = fmaf(oj.y, w0, gh0.y); gh0.z = fmaf(oj.z, w0, gh0.z); gh0.w = fmaf(oj.w, w0, gh0.w);
        gh1.x = fmaf(oj.x, w1, gh1.x); gh1.y = fmaf(oj.y, w1, gh1.y); gh1.z = fmaf(oj.z, w1, gh1.z); gh1.w = fmaf(oj.w, w1, gh1.w);
        gh2.x = fmaf(oj.x, w2, gh2.x); gh2.y = fmaf(oj.y, w2, gh2.y); gh2.z = fmaf(oj.z, w2, gh2.z); gh2.w = fmaf(oj.w, w2, gh2.w);
    }

    float4 hs = *(const float4*)&os_[d * 36 + nl];
    float r0 = gru_out(gi0.x, gh0.x, gi1.x, gh1.x, gi2.x, gh2.x, hs.x);
    float r1 = gru_out(gi0.y, gh0.y, gi1.y, gh1.y, gi2.y, gh2.y, hs.y);
    float r2 = gru_out(gi0.z, gh0.z, gi1.z, gh1.z, gi2.z, gh2.z, hs.z);
    float r3 = gru_out(gi0.w, gh0.w, gi1.w, gh1.w, gi2.w, gh2.w, hs.w);

    int base = n0 + nl;
    if (base + 0 < N) g_state[(base + 0) * DIM + f * ND + d] = r0;
    if (base + 1 < N) g_state[(base + 1) * DIM + f * ND + d] = r1;
    if (base + 2 < N) g_state[(base + 2) * DIM + f * ND + d] = r2;
    if (base + 3 < N) g_state[(base + 3) * DIM + f * ND + d] = r3;
}

// ------------------------- K7: segment-mean pooling ------------------------
__global__ __launch_bounds__(128) void k_pool(const int* __restrict__ batch,
                                              float* __restrict__ d_out) {
    int g = blockIdx.x;
    int c = threadIdx.x;
    int lo = 0, hi = N;
    while (lo < hi) { int mid = (lo + hi) >> 1; if (batch[mid] < g) lo = mid + 1; else hi = mid; }
    int s = lo;
    hi = N;
    while (lo < hi) { int mid = (lo + hi) >> 1; if (batch[mid] < g + 1) lo = mid + 1; else hi = mid; }
    int e = lo;
    float sum = 0.f;
    for (int n = s; n < e; n++) sum += g_state[n * DIM + c];
    float cnt = fmaxf((float)(e - s), 1.f);
    float val = __fdividef(sum, cnt);
    g_pooled[g * DIM + c] = val;
    int f = c >> 5, d = c & 31;
    d_out[OFF_OUTS + f * G * ND + g * ND + d] = val;
}

// ------------------------- K8: final MLP -----------------------------------
__global__ __launch_bounds__(128) void k_mlp(const float* __restrict__ fc1_W,
                                             const float* __restrict__ fc1_b,
                                             const float* __restrict__ fc2_W,
                                             const float* __restrict__ fc2_b,
                                             float* __restrict__ d_out) {
    __shared__ float oc[128];
    __shared__ float hid[128];
    int g = blockIdx.x, c = threadIdx.x;
    oc[c] = g_pooled[g * DIM + c];
    __syncthreads();
    float acc = fc1_b[c];
    for (int k = 0; k < DIM; k++) acc = fmaf(oc[k], fc1_W[k * DIM + c], acc);
    hid[c] = fmaxf(acc, 0.f);
    __syncthreads();
    if (c < NC) {
        float p = fc2_b[c];
        for (int k = 0; k < DIM; k++) p = fmaf(hid[k], fc2_W[k * NC + c], p);
        d_out[OFF_PRED + g * NC + c] = p;
    }
}

// ------------------------- launch ------------------------------------------
extern "C" void kernel_launch(void* const* d_in, const int* in_sizes, int n_in,
                              void* d_out_v, int out_size) {
    const float* x          = (const float*)d_in[0];
    const int*   ei         = (const int*)d_in[1];
    const int*   batch      = (const int*)d_in[2];
    const float* lin0_W     = (const float*)d_in[3];
    const float* lin0_b     = (const float*)d_in[4];
    const float* att_W      = (const float*)d_in[5];
    const float* att_b      = (const float*)d_in[6];
    const float* enc_W      = (const float*)d_in[7];
    const float* enc_b      = (const float*)d_in[8];
    const float* conv_Wrel  = (const float*)d_in[9];
    const float* conv_brel  = (const float*)d_in[10];
    const float* conv_Wroot = (const float*)d_in[11];
    const float* gru_Wih    = (const float*)d_in[12];
    const float* gru_Whh    = (const float*)d_in[13];
    const float* gru_bih    = (const float*)d_in[14];
    const float* gru_bhh    = (const float*)d_in[15];
    const float* fc1_W      = (const float*)d_in[16];
    const float* fc1_b      = (const float*)d_in[17];
    const float* fc2_W      = (const float*)d_in[18];
    const float* fc2_b      = (const float*)d_in[19];
    float* out = (float*)d_out_v;

    const int initSmem = (NF * F * ND + 2 * NF * F + F * NPB) * (int)sizeof(float);  // 77824
    cudaFuncSetAttribute(k_init, cudaFuncAttributeMaxDynamicSharedMemorySize, initSmem);

    k_pre<<<NF, 128>>>(lin0_W, lin0_b, att_W, att_b);
    k_init<<<(N + NPB - 1) / NPB, 128, initSmem>>>(x, enc_W, enc_b);
    k_att<<<(E + 255) / 256, 256>>>(ei, out + OFF_ATT);

    k_zero_cnt<<<(N + 255) / 256, 256>>>();
    k_hist<<<(E + 255) / 256, 256>>>(ei);
    k_scan<<<1, 1024>>>();
    k_scatter<<<(E + 255) / 256, 256>>>(ei);
    k_csratt<<<(E + 255) / 256, 256>>>();

    for (int l = 0; l < NL; l++) {
        k_agg<<<(N * 32 + 255) / 256, 256>>>();
        k_update<<<dim3((N + 31) / 32, NF), 256>>>(conv_Wrel, conv_brel, conv_Wroot,
                                                   gru_Wih, gru_Whh, gru_bih, gru_bhh, l);
    }

    k_pool<<<G, 128>>>(batch, out);
    k_mlp<<<G, 128>>>(fc1_W, fc1_b, fc2_W, fc2_b, out);
}